// round 12
// baseline (speedup 1.0000x reference)
#include <cuda_runtime.h>
#include <cuda_fp16.h>
#include <math.h>
#include <stdint.h>

// ---------------------------------------------------------------------------
// InterImageTokenizer — round 11.
// One fp16 m16n8k16 GEMM over B = [conv_w ; vocab_norm] (BN=128, 2 CTA/SM,
// 4-stage cp.async pipeline w/ 2-slab fetch-ahead, ldmatrix fragments).
// init_packed folded into extract; launches reordered so ncu captures GEMM.
// Fixed shapes: B=64, C=3, HW=384, P=16 -> N=576, D=Hd=768, V=1000.
// ---------------------------------------------------------------------------

constexpr int CB   = 64;
constexpr int CC   = 3;
constexpr int CHW  = 384;
constexpr int CP   = 16;
constexpr int CG   = CHW / CP;      // 24
constexpr int CN   = CG * CG;       // 576
constexpr int CD   = CC * CP * CP;  // 768
constexpr int CHD  = 768;
constexpr int CV   = 1000;
constexpr int CVP  = 1024;          // padded vocab rows
constexpr int CNB  = CHD + CVP;     // 1792 concatenated B rows
constexpr int CBN  = CB * CN;       // 36864
constexpr int CNP1 = CN + 1;        // 577

// -------------------- device scratch ---------------------------------------
__device__ __half g_patches[(size_t)CBN * CD];    // fp16, [M][K]
__device__ float  g_emb[(size_t)CBN * CHD];
__device__ __half g_Bcat[(size_t)CNB * CD];       // [conv_w ; vocab_norm] K-major
__device__ float  g_pnorm[CBN];
__device__ unsigned long long g_packed[CBN];      // (ordered_score<<32)|(~v)
__device__ int   g_perm[CB * CN];
__device__ int   g_segstart[CB * CNP1];
__device__ int   g_nseg[CB];

// -------------------- helpers ----------------------------------------------
__device__ __forceinline__ void mma_f16(float* c, const unsigned* a, const unsigned* b) {
    asm volatile(
        "mma.sync.aligned.m16n8k16.row.col.f32.f16.f16.f32 "
        "{%0,%1,%2,%3}, {%4,%5,%6,%7}, {%8,%9}, {%0,%1,%2,%3};"
        : "+f"(c[0]), "+f"(c[1]), "+f"(c[2]), "+f"(c[3])
        : "r"(a[0]), "r"(a[1]), "r"(a[2]), "r"(a[3]), "r"(b[0]), "r"(b[1]));
}
__device__ __forceinline__ void ldsm_x4(unsigned& r0, unsigned& r1, unsigned& r2,
                                        unsigned& r3, const void* p) {
    unsigned a = (unsigned)__cvta_generic_to_shared(p);
    asm volatile("ldmatrix.sync.aligned.m8n8.x4.shared.b16 {%0,%1,%2,%3}, [%4];"
                 : "=r"(r0), "=r"(r1), "=r"(r2), "=r"(r3) : "r"(a));
}
__device__ __forceinline__ void cp16(void* smem_dst, const void* gmem_src) {
    unsigned s = (unsigned)__cvta_generic_to_shared(smem_dst);
    asm volatile("cp.async.ca.shared.global [%0], [%1], 16;\n" :: "r"(s), "l"(gmem_src));
}
__device__ __forceinline__ unsigned enc_f(float f) {
    unsigned u = __float_as_uint(f);
    return (u & 0x80000000u) ? ~u : (u | 0x80000000u);
}
__device__ __forceinline__ float dec_f(unsigned e) {
    unsigned b = (e & 0x80000000u) ? (e ^ 0x80000000u) : ~e;
    return __uint_as_float(b);
}

// -------------------- prep: normalize vocab -> fp16 into g_Bcat[768+] -------
__global__ void prep_vocab_kernel(const float* __restrict__ vocab) {
    int v = blockIdx.x;
    __half* dst = &g_Bcat[(size_t)(CHD + v) * CD];
    if (v >= CV) {
        for (int d = threadIdx.x; d < CD; d += 256) dst[d] = __float2half_rn(0.f);
        return;
    }
    __shared__ float red[256];
    float s = 0.f;
    for (int d = threadIdx.x; d < CD; d += 256) {
        float x = vocab[(size_t)v * CD + d];
        s += x * x;
    }
    red[threadIdx.x] = s; __syncthreads();
    for (int o = 128; o > 0; o >>= 1) {
        if (threadIdx.x < o) red[threadIdx.x] += red[threadIdx.x + o];
        __syncthreads();
    }
    float invn = 1.0f / sqrtf(red[0]);
    for (int d = threadIdx.x; d < CD; d += 256)
        dst[d] = __float2half_rn(vocab[(size_t)v * CD + d] * invn);
}

// -------------------- prep: conv weight -> fp16 into g_Bcat[0..768) ---------
__global__ void conv_w_half_kernel(const float* __restrict__ W) {
    int i = blockIdx.x * 256 + threadIdx.x;
    if (i < CHD * CD) g_Bcat[i] = __float2half_rn(W[i]);
}

// -------------------- fused patch extraction + L2 norm + packed init --------
__global__ void __launch_bounds__(192) extract_pnorm_kernel(const float* __restrict__ px) {
    int patch = blockIdx.x;               // 0..CBN-1
    int b = patch / CN, n = patch % CN;
    int hp = n / CG, wp = n % CG;
    const float* base = px + ((size_t)b * CC * CHW + (size_t)hp * CP) * CHW + wp * CP;
    int tid = threadIdx.x, lane = tid & 31, w = tid >> 5;
    if (tid == 64) g_packed[patch] = 0ULL;     // zero before GEMM (stream-ordered)
    int d4 = tid << 2;
    int c = d4 >> 8, r = d4 & 255, ph = r >> 4, pw = r & 15;
    float4 x = *reinterpret_cast<const float4*>(
        &base[((size_t)c * CHW + ph) * CHW + pw]);
    __half2 h01 = __floats2half2_rn(x.x, x.y);
    __half2 h23 = __floats2half2_rn(x.z, x.w);
    *reinterpret_cast<uint2*>(&g_patches[(size_t)patch * CD + d4]) =
        make_uint2(*reinterpret_cast<unsigned*>(&h01), *reinterpret_cast<unsigned*>(&h23));
    float ss = x.x * x.x + x.y * x.y + x.z * x.z + x.w * x.w;
#pragma unroll
    for (int o = 16; o > 0; o >>= 1) ss += __shfl_xor_sync(0xffffffffu, ss, o);
    __shared__ float ws[6];
    if (lane == 0) ws[w] = ss;
    __syncthreads();
    if (tid == 0) {
        float t = ws[0] + ws[1] + ws[2] + ws[3] + ws[4] + ws[5];
        g_pnorm[patch] = sqrtf(t);
    }
}

// -------------------- GEMM config -------------------------------------------
#define BM 128
#define BN 128
#define BK 32
#define PAD_ST 40
#define NSTAGE 4
constexpr int SM_A_H = BM * PAD_ST;     // 5120 halves per stage
constexpr int SM_B_H = BN * PAD_ST;     // 5120 halves per stage
constexpr int SMEM_GEMM = NSTAGE * (SM_A_H + SM_B_H) * 2;  // 81920 B

__global__ void __launch_bounds__(256, 2)
gemm_fused_kernel(const __half* __restrict__ A, const __half* __restrict__ Bg,
                  float* __restrict__ C, const float* __restrict__ bias,
                  const float* __restrict__ pos) {
    extern __shared__ __half sm[];
    __half* AsB = sm;                        // [NSTAGE][BM][PAD_ST]
    __half* BsB = sm + NSTAGE * SM_A_H;      // [NSTAGE][BN][PAD_ST]
    int tid = threadIdx.x, lane = tid & 31, warp = tid >> 5;
    int warpM = warp >> 2, warpN = warp & 3;
    int rowBase = blockIdx.y * BM, colBase = blockIdx.x * BN;
    int tig = lane & 3, grp = lane >> 2;
    int lrow = lane & 15, lhi = (lane >> 4) << 3;

    float acc[4][4][4];
#pragma unroll
    for (int mi = 0; mi < 4; mi++)
#pragma unroll
        for (int ni = 0; ni < 4; ni++)
#pragma unroll
            for (int q = 0; q < 4; q++) acc[mi][ni][q] = 0.f;

    const int nk = CD / BK;  // 24

#define G_LOAD(ST, K0)                                                               \
    {                                                                                \
        _Pragma("unroll")                                                            \
        for (int i = 0; i < 2; i++) {                                                \
            int idx = tid + i * 256;                                                 \
            int r = idx >> 2, c8 = (idx & 3) << 3;                                   \
            cp16(&AsB[(ST) * SM_A_H + r * PAD_ST + c8],                              \
                 &A[(size_t)(rowBase + r) * CD + (K0) + c8]);                        \
        }                                                                            \
        _Pragma("unroll")                                                            \
        for (int i = 0; i < 2; i++) {                                                \
            int idx = tid + i * 256;                                                 \
            int r = idx >> 2, c8 = (idx & 3) << 3;                                   \
            cp16(&BsB[(ST) * SM_B_H + r * PAD_ST + c8],                              \
                 &Bg[(size_t)(colBase + r) * CD + (K0) + c8]);                       \
        }                                                                            \
        asm volatile("cp.async.commit_group;\n");                                    \
    }

    G_LOAD(0, 0);
    G_LOAD(1, BK);
    G_LOAD(2, 2 * BK);
    for (int kt = 0; kt < nk; kt++) {
        if (kt < nk - 2) {
            asm volatile("cp.async.wait_group 2;\n");
        } else if (kt == nk - 2) {
            asm volatile("cp.async.wait_group 1;\n");
        } else {
            asm volatile("cp.async.wait_group 0;\n");
        }
        __syncthreads();
        if (kt + 3 < nk) {
            int st3 = (kt + 3) & (NSTAGE - 1);
            G_LOAD(st3, (kt + 3) * BK);
        }
        int st = kt & (NSTAGE - 1);
        const __half* Asm = &AsB[st * SM_A_H];
        const __half* Bsm = &BsB[st * SM_B_H];
#pragma unroll
        for (int kk = 0; kk < 2; kk++) {
            int kb = kk * 16;
            unsigned ua[4][4], ub[4][2];
#pragma unroll
            for (int mi = 0; mi < 4; mi++) {
                ldsm_x4(ua[mi][0], ua[mi][1], ua[mi][2], ua[mi][3],
                        &Asm[(warpM * 64 + mi * 16 + lrow) * PAD_ST + kb + lhi]);
            }
#pragma unroll
            for (int p = 0; p < 2; p++) {
                ldsm_x4(ub[2 * p][0], ub[2 * p + 1][0], ub[2 * p][1], ub[2 * p + 1][1],
                        &Bsm[(warpN * 32 + p * 16 + lrow) * PAD_ST + kb + lhi]);
            }
#pragma unroll
            for (int mi = 0; mi < 4; mi++)
#pragma unroll
                for (int ni = 0; ni < 4; ni++)
                    mma_f16(acc[mi][ni], ua[mi], ub[ni]);
        }
    }
#undef G_LOAD

    if (colBase < CHD) {
        // ---- emb epilogue: C = acc + bias + pos ----
#pragma unroll
        for (int mi = 0; mi < 4; mi++) {
            int r0 = rowBase + warpM * 64 + mi * 16 + grp;
            int r1 = r0 + 8;
            int p0 = (r0 % CN) + 1, p1 = (r1 % CN) + 1;
#pragma unroll
            for (int ni = 0; ni < 4; ni++) {
                int col = colBase + warpN * 32 + ni * 8 + 2 * tig;
                float2 v0, v1;
                v0.x = acc[mi][ni][0] + bias[col]     + pos[(size_t)p0 * CHD + col];
                v0.y = acc[mi][ni][1] + bias[col + 1] + pos[(size_t)p0 * CHD + col + 1];
                v1.x = acc[mi][ni][2] + bias[col]     + pos[(size_t)p1 * CHD + col];
                v1.y = acc[mi][ni][3] + bias[col + 1] + pos[(size_t)p1 * CHD + col + 1];
                *reinterpret_cast<float2*>(&C[(size_t)r0 * CHD + col]) = v0;
                *reinterpret_cast<float2*>(&C[(size_t)r1 * CHD + col]) = v1;
            }
        }
    } else {
        // ---- scores epilogue: fused per-row max/argmax (ties -> smallest v) ----
        int vcolBase = colBase - CHD;
#pragma unroll
        for (int mi = 0; mi < 4; mi++) {
#pragma unroll
            for (int h = 0; h < 2; h++) {
                int row = rowBase + warpM * 64 + mi * 16 + h * 8 + grp;
                unsigned long long p = 0ULL;
#pragma unroll
                for (int ni = 0; ni < 4; ni++) {
                    int col = vcolBase + warpN * 32 + ni * 8 + 2 * tig;
                    float s0 = acc[mi][ni][h * 2 + 0];
                    float s1 = acc[mi][ni][h * 2 + 1];
                    if (col < CV) {
                        unsigned long long q =
                            ((unsigned long long)enc_f(s0) << 32) | (0xFFFFFFFFu - (unsigned)col);
                        if (q > p) p = q;
                    }
                    if (col + 1 < CV) {
                        unsigned long long q =
                            ((unsigned long long)enc_f(s1) << 32) | (0xFFFFFFFFu - (unsigned)(col + 1));
                        if (q > p) p = q;
                    }
                }
                unsigned long long o;
                o = __shfl_xor_sync(0xffffffffu, p, 1); if (o > p) p = o;
                o = __shfl_xor_sync(0xffffffffu, p, 2); if (o > p) p = o;
                if (tig == 0 && p) atomicMax(&g_packed[row], p);
            }
        }
    }
}

// -------------------- fused label + per-row sort + unique-consecutive --------
// Fresh ids use a PER-ROW base (CV + row-local rank): compaction only depends
// on within-row order/equality, fresh ids stay distinct, > V-1, n-ordered —
// identical compact labels to the reference's global cumsum.
__global__ void __launch_bounds__(1024)
compact_kernel(float* __restrict__ labels_out) {
    __shared__ unsigned int key[1024];
    __shared__ int sc[1024];
    int b = blockIdx.x, tid = threadIdx.x;

    // mask + per-row prefix to build raw labels
    int m = 0, v = 0;
    if (tid < CN) {
        unsigned long long p = g_packed[b * CN + tid];
        float score = dec_f((unsigned)(p >> 32));
        v = (int)(0xFFFFFFFFu - (unsigned)(p & 0xFFFFFFFFu));
        float smin = 1.0f - score / g_pnorm[b * CN + tid];
        m = (smin > 0.1f) ? 1 : 0;
    }
    sc[tid] = m; __syncthreads();
    for (int off = 1; off < 1024; off <<= 1) {
        int y = (tid >= off) ? sc[tid - off] : 0;
        __syncthreads();
        sc[tid] += y;
        __syncthreads();
    }
    int lab0 = m ? (CV + sc[tid] - m) : v;
    key[tid] = (tid < CN) ? ((((unsigned)lab0) << 16) | (unsigned)tid) : 0xFFFFFFFFu;
    __syncthreads();

    for (int k = 2; k <= 1024; k <<= 1) {
        for (int j = k >> 1; j > 0; j >>= 1) {
            int ixj = tid ^ j;
            if (ixj > tid) {
                unsigned a = key[tid], c2 = key[ixj];
                bool up = ((tid & k) == 0);
                if ((a > c2) == up) { key[tid] = c2; key[ixj] = a; }
            }
            __syncthreads();
        }
    }

    int lab     = (int)(key[tid] >> 16);
    int labprev = (tid > 0) ? (int)(key[tid - 1] >> 16) : -1;
    int step = (tid > 0 && tid < CN && lab != labprev) ? 1 : 0;
    sc[tid] = step; __syncthreads();
    for (int off = 1; off < 1024; off <<= 1) {
        int y = (tid >= off) ? sc[tid - off] : 0;
        __syncthreads();
        sc[tid] += y;
        __syncthreads();
    }
    if (tid < CN) {
        int l = sc[tid];
        int orig = (int)(key[tid] & 0xFFFFu);
        labels_out[(size_t)b * CN + orig] = (float)l;
        g_perm[b * CN + tid] = orig;
        if (tid == 0 || step) g_segstart[b * CNP1 + l] = tid;
    }
    __syncthreads();
    if (tid == 0) {
        int ns = sc[CN - 1] + 1;
        g_nseg[b] = ns;
        g_segstart[b * CNP1 + ns] = CN;
    }
}

// -------------------- segment means + cls + pad ------------------------------
__global__ void means_kernel(float* __restrict__ out, const float* __restrict__ cls,
                             const float* __restrict__ pos, const float* __restrict__ pad) {
    int b = blockIdx.y, r = blockIdx.x;
    float* o = out + ((size_t)b * CNP1 + r) * CHD;
    if (r == 0) {
        for (int h = threadIdx.x; h < CHD; h += blockDim.x)
            o[h] = cls[h] + pos[h];
        return;
    }
    int l = r - 1;
    if (l < g_nseg[b]) {
        int s0 = g_segstart[b * CNP1 + l];
        int s1 = g_segstart[b * CNP1 + l + 1];
        float cnt = (float)(s1 - s0);
        for (int h = threadIdx.x; h < CHD; h += blockDim.x) {
            float s = 0.f;
            for (int j = s0; j < s1; j++)
                s += g_emb[((size_t)b * CN + g_perm[b * CN + j]) * CHD + h];
            o[h] = s / cnt;
        }
    } else {
        for (int h = threadIdx.x; h < CHD; h += blockDim.x)
            o[h] = pad[h];
    }
}

// -------------------- attention mask -----------------------------------------
__global__ void attn_kernel(float* __restrict__ attn) {
    size_t idx = (size_t)blockIdx.x * blockDim.x + threadIdx.x;
    size_t total = (size_t)CB * CNP1 * CNP1;
    if (idx >= total) return;
    int j = (int)(idx % CNP1);
    int b = (int)(idx / ((size_t)CNP1 * CNP1));
    float v = 0.0f;
    if (j > 0 && (j - 1) >= g_nseg[b]) v = -3.4028234663852886e38f;  // -FLT_MAX
    attn[idx] = v;
}

// ---------------------------------------------------------------------------
extern "C" void kernel_launch(void* const* d_in, const int* in_sizes, int n_in,
                              void* d_out, int out_size) {
    (void)in_sizes; (void)n_in; (void)out_size;
    const float* px     = (const float*)d_in[0];
    const float* conv_w = (const float*)d_in[1];
    const float* conv_b = (const float*)d_in[2];
    const float* cls    = (const float*)d_in[3];
    const float* pos    = (const float*)d_in[4];
    const float* vocab  = (const float*)d_in[5];
    const float* pad    = (const float*)d_in[6];

    float* out        = (float*)d_out;
    float* labels_out = out + (size_t)CB * CNP1 * CHD;
    float* attn_out   = labels_out + (size_t)CB * CN;

    __half *patches, *Bcat;
    float *emb;
    cudaGetSymbolAddress((void**)&patches, g_patches);
    cudaGetSymbolAddress((void**)&emb,     g_emb);
    cudaGetSymbolAddress((void**)&Bcat,    g_Bcat);

    cudaFuncSetAttribute(gemm_fused_kernel,
                         cudaFuncAttributeMaxDynamicSharedMemorySize, SMEM_GEMM);

    // order matters for the ncu fixed-index capture: gemm is launch #3
    prep_vocab_kernel<<<CVP, 256>>>(vocab);
    conv_w_half_kernel<<<(CHD * CD + 255) / 256, 256>>>(conv_w);
    extract_pnorm_kernel<<<CBN, 192>>>(px);
    gemm_fused_kernel<<<dim3(CNB / BN, CBN / BM), 256, SMEM_GEMM>>>(
        patches, Bcat, emb, conv_b, pos);

    compact_kernel<<<CB, 1024>>>(labels_out);
    means_kernel<<<dim3(CNP1, CB), 256>>>(out, cls, pos, pad);

    {
        size_t total = (size_t)CB * CNP1 * CNP1;
        attn_kernel<<<(unsigned)((total + 255) / 256), 256>>>(attn_out);
    }
}

// round 13
// speedup vs baseline: 1.0076x; 1.0076x over previous
#include <cuda_runtime.h>
#include <cuda_fp16.h>
#include <math.h>
#include <stdint.h>

// ---------------------------------------------------------------------------
// InterImageTokenizer — round 12.
// fp16 m16n8k16 GEMM over B = [conv_w ; vocab_norm] (BN=128, 2 CTA/SM,
// NSTAGE=3 cp.async pipeline, batched ldmatrix: all 12 LDSM then 32 HMMA
// per K-slab to maximize L1-pipe utilization (profiled L1-bound at 76%).
// Fixed shapes: B=64, C=3, HW=384, P=16 -> N=576, D=Hd=768, V=1000.
// ---------------------------------------------------------------------------

constexpr int CB   = 64;
constexpr int CC   = 3;
constexpr int CHW  = 384;
constexpr int CP   = 16;
constexpr int CG   = CHW / CP;      // 24
constexpr int CN   = CG * CG;       // 576
constexpr int CD   = CC * CP * CP;  // 768
constexpr int CHD  = 768;
constexpr int CV   = 1000;
constexpr int CVP  = 1024;          // padded vocab rows
constexpr int CNB  = CHD + CVP;     // 1792 concatenated B rows
constexpr int CBN  = CB * CN;       // 36864
constexpr int CNP1 = CN + 1;        // 577

// -------------------- device scratch ---------------------------------------
__device__ __half g_patches[(size_t)CBN * CD];    // fp16, [M][K]
__device__ float  g_emb[(size_t)CBN * CHD];
__device__ __half g_Bcat[(size_t)CNB * CD];       // [conv_w ; vocab_norm] K-major
__device__ float  g_pnorm[CBN];
__device__ unsigned long long g_packed[CBN];      // (ordered_score<<32)|(~v)
__device__ int   g_perm[CB * CN];
__device__ int   g_segstart[CB * CNP1];
__device__ int   g_nseg[CB];

// -------------------- helpers ----------------------------------------------
__device__ __forceinline__ void mma_f16(float* c, const unsigned* a, const unsigned* b) {
    asm volatile(
        "mma.sync.aligned.m16n8k16.row.col.f32.f16.f16.f32 "
        "{%0,%1,%2,%3}, {%4,%5,%6,%7}, {%8,%9}, {%0,%1,%2,%3};"
        : "+f"(c[0]), "+f"(c[1]), "+f"(c[2]), "+f"(c[3])
        : "r"(a[0]), "r"(a[1]), "r"(a[2]), "r"(a[3]), "r"(b[0]), "r"(b[1]));
}
__device__ __forceinline__ void ldsm_x4(unsigned& r0, unsigned& r1, unsigned& r2,
                                        unsigned& r3, const void* p) {
    unsigned a = (unsigned)__cvta_generic_to_shared(p);
    asm volatile("ldmatrix.sync.aligned.m8n8.x4.shared.b16 {%0,%1,%2,%3}, [%4];"
                 : "=r"(r0), "=r"(r1), "=r"(r2), "=r"(r3) : "r"(a));
}
__device__ __forceinline__ void cp16(void* smem_dst, const void* gmem_src) {
    unsigned s = (unsigned)__cvta_generic_to_shared(smem_dst);
    asm volatile("cp.async.ca.shared.global [%0], [%1], 16;\n" :: "r"(s), "l"(gmem_src));
}
__device__ __forceinline__ unsigned enc_f(float f) {
    unsigned u = __float_as_uint(f);
    return (u & 0x80000000u) ? ~u : (u | 0x80000000u);
}
__device__ __forceinline__ float dec_f(unsigned e) {
    unsigned b = (e & 0x80000000u) ? (e ^ 0x80000000u) : ~e;
    return __uint_as_float(b);
}

// -------------------- prep: normalize vocab -> fp16 into g_Bcat[768+] -------
__global__ void prep_vocab_kernel(const float* __restrict__ vocab) {
    int v = blockIdx.x;
    __half* dst = &g_Bcat[(size_t)(CHD + v) * CD];
    if (v >= CV) {
        for (int d = threadIdx.x; d < CD; d += 256) dst[d] = __float2half_rn(0.f);
        return;
    }
    __shared__ float red[256];
    float s = 0.f;
    for (int d = threadIdx.x; d < CD; d += 256) {
        float x = vocab[(size_t)v * CD + d];
        s += x * x;
    }
    red[threadIdx.x] = s; __syncthreads();
    for (int o = 128; o > 0; o >>= 1) {
        if (threadIdx.x < o) red[threadIdx.x] += red[threadIdx.x + o];
        __syncthreads();
    }
    float invn = 1.0f / sqrtf(red[0]);
    for (int d = threadIdx.x; d < CD; d += 256)
        dst[d] = __float2half_rn(vocab[(size_t)v * CD + d] * invn);
}

// -------------------- prep: conv weight -> fp16 into g_Bcat[0..768) ---------
__global__ void conv_w_half_kernel(const float* __restrict__ W) {
    int i = blockIdx.x * 256 + threadIdx.x;
    if (i < CHD * CD) g_Bcat[i] = __float2half_rn(W[i]);
}

// -------------------- fused patch extraction + L2 norm + packed init --------
__global__ void __launch_bounds__(192) extract_pnorm_kernel(const float* __restrict__ px) {
    int patch = blockIdx.x;               // 0..CBN-1
    int b = patch / CN, n = patch % CN;
    int hp = n / CG, wp = n % CG;
    const float* base = px + ((size_t)b * CC * CHW + (size_t)hp * CP) * CHW + wp * CP;
    int tid = threadIdx.x, lane = tid & 31, w = tid >> 5;
    if (tid == 64) g_packed[patch] = 0ULL;     // zero before GEMM (stream-ordered)
    int d4 = tid << 2;
    int c = d4 >> 8, r = d4 & 255, ph = r >> 4, pw = r & 15;
    float4 x = *reinterpret_cast<const float4*>(
        &base[((size_t)c * CHW + ph) * CHW + pw]);
    __half2 h01 = __floats2half2_rn(x.x, x.y);
    __half2 h23 = __floats2half2_rn(x.z, x.w);
    *reinterpret_cast<uint2*>(&g_patches[(size_t)patch * CD + d4]) =
        make_uint2(*reinterpret_cast<unsigned*>(&h01), *reinterpret_cast<unsigned*>(&h23));
    float ss = x.x * x.x + x.y * x.y + x.z * x.z + x.w * x.w;
#pragma unroll
    for (int o = 16; o > 0; o >>= 1) ss += __shfl_xor_sync(0xffffffffu, ss, o);
    __shared__ float ws[6];
    if (lane == 0) ws[w] = ss;
    __syncthreads();
    if (tid == 0) {
        float t = ws[0] + ws[1] + ws[2] + ws[3] + ws[4] + ws[5];
        g_pnorm[patch] = sqrtf(t);
    }
}

// -------------------- GEMM config -------------------------------------------
#define BM 128
#define BN 128
#define BK 32
#define PAD_ST 40
#define NSTAGE 3
constexpr int SM_A_H = BM * PAD_ST;     // 5120 halves per stage
constexpr int SM_B_H = BN * PAD_ST;     // 5120 halves per stage
constexpr int SMEM_GEMM = NSTAGE * (SM_A_H + SM_B_H) * 2;  // 61440 B

__global__ void __launch_bounds__(256, 2)
gemm_fused_kernel(const __half* __restrict__ A, const __half* __restrict__ Bg,
                  float* __restrict__ C, const float* __restrict__ bias,
                  const float* __restrict__ pos) {
    extern __shared__ __half sm[];
    __half* AsB = sm;                        // [NSTAGE][BM][PAD_ST]
    __half* BsB = sm + NSTAGE * SM_A_H;      // [NSTAGE][BN][PAD_ST]
    int tid = threadIdx.x, lane = tid & 31, warp = tid >> 5;
    int warpM = warp >> 2, warpN = warp & 3;
    int rowBase = blockIdx.y * BM, colBase = blockIdx.x * BN;
    int tig = lane & 3, grp = lane >> 2;
    int lrow = lane & 15, lhi = (lane >> 4) << 3;

    float acc[4][4][4];
#pragma unroll
    for (int mi = 0; mi < 4; mi++)
#pragma unroll
        for (int ni = 0; ni < 4; ni++)
#pragma unroll
            for (int q = 0; q < 4; q++) acc[mi][ni][q] = 0.f;

    const int nk = CD / BK;  // 24

#define G_LOAD(ST, K0)                                                               \
    {                                                                                \
        _Pragma("unroll")                                                            \
        for (int i = 0; i < 2; i++) {                                                \
            int idx = tid + i * 256;                                                 \
            int r = idx >> 2, c8 = (idx & 3) << 3;                                   \
            cp16(&AsB[(ST) * SM_A_H + r * PAD_ST + c8],                              \
                 &A[(size_t)(rowBase + r) * CD + (K0) + c8]);                        \
        }                                                                            \
        _Pragma("unroll")                                                            \
        for (int i = 0; i < 2; i++) {                                                \
            int idx = tid + i * 256;                                                 \
            int r = idx >> 2, c8 = (idx & 3) << 3;                                   \
            cp16(&BsB[(ST) * SM_B_H + r * PAD_ST + c8],                              \
                 &Bg[(size_t)(colBase + r) * CD + (K0) + c8]);                       \
        }                                                                            \
        asm volatile("cp.async.commit_group;\n");                                    \
    }

    G_LOAD(0, 0);
    G_LOAD(1, BK);
    for (int kt = 0; kt < nk; kt++) {
        if (kt + 1 < nk) {
            asm volatile("cp.async.wait_group 1;\n");
        } else {
            asm volatile("cp.async.wait_group 0;\n");
        }
        __syncthreads();
        if (kt + 2 < nk) {
            int st2 = (kt + 2) % NSTAGE;
            G_LOAD(st2, (kt + 2) * BK);
        }
        int st = kt % NSTAGE;
        const __half* Asm = &AsB[st * SM_A_H];
        const __half* Bsm = &BsB[st * SM_B_H];
        // batched fragment loads for BOTH kk sub-steps, then all mma —
        // keeps the L1 pipe streaming instead of LDS/HMMA ping-pong.
        unsigned ua[2][4][4], ub[2][4][2];
#pragma unroll
        for (int kk = 0; kk < 2; kk++) {
            int kb = kk * 16;
#pragma unroll
            for (int mi = 0; mi < 4; mi++) {
                ldsm_x4(ua[kk][mi][0], ua[kk][mi][1], ua[kk][mi][2], ua[kk][mi][3],
                        &Asm[(warpM * 64 + mi * 16 + lrow) * PAD_ST + kb + lhi]);
            }
#pragma unroll
            for (int p = 0; p < 2; p++) {
                ldsm_x4(ub[kk][2 * p][0], ub[kk][2 * p + 1][0],
                        ub[kk][2 * p][1], ub[kk][2 * p + 1][1],
                        &Bsm[(warpN * 32 + p * 16 + lrow) * PAD_ST + kb + lhi]);
            }
        }
#pragma unroll
        for (int kk = 0; kk < 2; kk++)
#pragma unroll
            for (int mi = 0; mi < 4; mi++)
#pragma unroll
                for (int ni = 0; ni < 4; ni++)
                    mma_f16(acc[mi][ni], ua[kk][mi], ub[kk][ni]);
    }
#undef G_LOAD

    if (colBase < CHD) {
        // ---- emb epilogue: C = acc + bias + pos ----
#pragma unroll
        for (int mi = 0; mi < 4; mi++) {
            int r0 = rowBase + warpM * 64 + mi * 16 + grp;
            int r1 = r0 + 8;
            int p0 = (r0 % CN) + 1, p1 = (r1 % CN) + 1;
#pragma unroll
            for (int ni = 0; ni < 4; ni++) {
                int col = colBase + warpN * 32 + ni * 8 + 2 * tig;
                float2 v0, v1;
                v0.x = acc[mi][ni][0] + bias[col]     + pos[(size_t)p0 * CHD + col];
                v0.y = acc[mi][ni][1] + bias[col + 1] + pos[(size_t)p0 * CHD + col + 1];
                v1.x = acc[mi][ni][2] + bias[col]     + pos[(size_t)p1 * CHD + col];
                v1.y = acc[mi][ni][3] + bias[col + 1] + pos[(size_t)p1 * CHD + col + 1];
                *reinterpret_cast<float2*>(&C[(size_t)r0 * CHD + col]) = v0;
                *reinterpret_cast<float2*>(&C[(size_t)r1 * CHD + col]) = v1;
            }
        }
    } else {
        // ---- scores epilogue: fused per-row max/argmax (ties -> smallest v) ----
        int vcolBase = colBase - CHD;
#pragma unroll
        for (int mi = 0; mi < 4; mi++) {
#pragma unroll
            for (int h = 0; h < 2; h++) {
                int row = rowBase + warpM * 64 + mi * 16 + h * 8 + grp;
                unsigned long long p = 0ULL;
#pragma unroll
                for (int ni = 0; ni < 4; ni++) {
                    int col = vcolBase + warpN * 32 + ni * 8 + 2 * tig;
                    float s0 = acc[mi][ni][h * 2 + 0];
                    float s1 = acc[mi][ni][h * 2 + 1];
                    if (col < CV) {
                        unsigned long long q =
                            ((unsigned long long)enc_f(s0) << 32) | (0xFFFFFFFFu - (unsigned)col);
                        if (q > p) p = q;
                    }
                    if (col + 1 < CV) {
                        unsigned long long q =
                            ((unsigned long long)enc_f(s1) << 32) | (0xFFFFFFFFu - (unsigned)(col + 1));
                        if (q > p) p = q;
                    }
                }
                unsigned long long o;
                o = __shfl_xor_sync(0xffffffffu, p, 1); if (o > p) p = o;
                o = __shfl_xor_sync(0xffffffffu, p, 2); if (o > p) p = o;
                if (tig == 0 && p) atomicMax(&g_packed[row], p);
            }
        }
    }
}

// -------------------- fused label + per-row sort + unique-consecutive --------
// Fresh ids use a PER-ROW base (CV + row-local rank): compaction only depends
// on within-row order/equality, fresh ids stay distinct, > V-1, n-ordered —
// identical compact labels to the reference's global cumsum.
__global__ void __launch_bounds__(1024)
compact_kernel(float* __restrict__ labels_out) {
    __shared__ unsigned int key[1024];
    __shared__ int sc[1024];
    int b = blockIdx.x, tid = threadIdx.x;

    // mask + per-row prefix to build raw labels
    int m = 0, v = 0;
    if (tid < CN) {
        unsigned long long p = g_packed[b * CN + tid];
        float score = dec_f((unsigned)(p >> 32));
        v = (int)(0xFFFFFFFFu - (unsigned)(p & 0xFFFFFFFFu));
        float smin = 1.0f - score / g_pnorm[b * CN + tid];
        m = (smin > 0.1f) ? 1 : 0;
    }
    sc[tid] = m; __syncthreads();
    for (int off = 1; off < 1024; off <<= 1) {
        int y = (tid >= off) ? sc[tid - off] : 0;
        __syncthreads();
        sc[tid] += y;
        __syncthreads();
    }
    int lab0 = m ? (CV + sc[tid] - m) : v;
    key[tid] = (tid < CN) ? ((((unsigned)lab0) << 16) | (unsigned)tid) : 0xFFFFFFFFu;
    __syncthreads();

    for (int k = 2; k <= 1024; k <<= 1) {
        for (int j = k >> 1; j > 0; j >>= 1) {
            int ixj = tid ^ j;
            if (ixj > tid) {
                unsigned a = key[tid], c2 = key[ixj];
                bool up = ((tid & k) == 0);
                if ((a > c2) == up) { key[tid] = c2; key[ixj] = a; }
            }
            __syncthreads();
        }
    }

    int lab     = (int)(key[tid] >> 16);
    int labprev = (tid > 0) ? (int)(key[tid - 1] >> 16) : -1;
    int step = (tid > 0 && tid < CN && lab != labprev) ? 1 : 0;
    sc[tid] = step; __syncthreads();
    for (int off = 1; off < 1024; off <<= 1) {
        int y = (tid >= off) ? sc[tid - off] : 0;
        __syncthreads();
        sc[tid] += y;
        __syncthreads();
    }
    if (tid < CN) {
        int l = sc[tid];
        int orig = (int)(key[tid] & 0xFFFFu);
        labels_out[(size_t)b * CN + orig] = (float)l;
        g_perm[b * CN + tid] = orig;
        if (tid == 0 || step) g_segstart[b * CNP1 + l] = tid;
    }
    __syncthreads();
    if (tid == 0) {
        int ns = sc[CN - 1] + 1;
        g_nseg[b] = ns;
        g_segstart[b * CNP1 + ns] = CN;
    }
}

// -------------------- segment means + cls + pad ------------------------------
__global__ void means_kernel(float* __restrict__ out, const float* __restrict__ cls,
                             const float* __restrict__ pos, const float* __restrict__ pad) {
    int b = blockIdx.y, r = blockIdx.x;
    float* o = out + ((size_t)b * CNP1 + r) * CHD;
    if (r == 0) {
        for (int h = threadIdx.x; h < CHD; h += blockDim.x)
            o[h] = cls[h] + pos[h];
        return;
    }
    int l = r - 1;
    if (l < g_nseg[b]) {
        int s0 = g_segstart[b * CNP1 + l];
        int s1 = g_segstart[b * CNP1 + l + 1];
        float cnt = (float)(s1 - s0);
        for (int h = threadIdx.x; h < CHD; h += blockDim.x) {
            float s = 0.f;
            for (int j = s0; j < s1; j++)
                s += g_emb[((size_t)b * CN + g_perm[b * CN + j]) * CHD + h];
            o[h] = s / cnt;
        }
    } else {
        for (int h = threadIdx.x; h < CHD; h += blockDim.x)
            o[h] = pad[h];
    }
}

// -------------------- attention mask -----------------------------------------
__global__ void attn_kernel(float* __restrict__ attn) {
    size_t idx = (size_t)blockIdx.x * blockDim.x + threadIdx.x;
    size_t total = (size_t)CB * CNP1 * CNP1;
    if (idx >= total) return;
    int j = (int)(idx % CNP1);
    int b = (int)(idx / ((size_t)CNP1 * CNP1));
    float v = 0.0f;
    if (j > 0 && (j - 1) >= g_nseg[b]) v = -3.4028234663852886e38f;  // -FLT_MAX
    attn[idx] = v;
}

// ---------------------------------------------------------------------------
extern "C" void kernel_launch(void* const* d_in, const int* in_sizes, int n_in,
                              void* d_out, int out_size) {
    (void)in_sizes; (void)n_in; (void)out_size;
    const float* px     = (const float*)d_in[0];
    const float* conv_w = (const float*)d_in[1];
    const float* conv_b = (const float*)d_in[2];
    const float* cls    = (const float*)d_in[3];
    const float* pos    = (const float*)d_in[4];
    const float* vocab  = (const float*)d_in[5];
    const float* pad    = (const float*)d_in[6];

    float* out        = (float*)d_out;
    float* labels_out = out + (size_t)CB * CNP1 * CHD;
    float* attn_out   = labels_out + (size_t)CB * CN;

    __half *patches, *Bcat;
    float *emb;
    cudaGetSymbolAddress((void**)&patches, g_patches);
    cudaGetSymbolAddress((void**)&emb,     g_emb);
    cudaGetSymbolAddress((void**)&Bcat,    g_Bcat);

    cudaFuncSetAttribute(gemm_fused_kernel,
                         cudaFuncAttributeMaxDynamicSharedMemorySize, SMEM_GEMM);

    // order matters for the ncu fixed-index capture: gemm is launch #3
    prep_vocab_kernel<<<CVP, 256>>>(vocab);
    conv_w_half_kernel<<<(CHD * CD + 255) / 256, 256>>>(conv_w);
    extract_pnorm_kernel<<<CBN, 192>>>(px);
    gemm_fused_kernel<<<dim3(CNB / BN, CBN / BM), 256, SMEM_GEMM>>>(
        patches, Bcat, emb, conv_b, pos);

    compact_kernel<<<CB, 1024>>>(labels_out);
    means_kernel<<<dim3(CNP1, CB), 256>>>(out, cls, pos, pad);

    {
        size_t total = (size_t)CB * CNP1 * CNP1;
        attn_kernel<<<(unsigned)((total + 255) / 256), 256>>>(attn_out);
    }
}

// round 14
// speedup vs baseline: 1.1963x; 1.1872x over previous
#include <cuda_runtime.h>
#include <cuda_fp16.h>
#include <math.h>
#include <stdint.h>

// ---------------------------------------------------------------------------
// InterImageTokenizer — round 13.
// GEMM frozen at round-12 best (354us). Non-GEMM epilogue optimized:
// attn merged into means (same grid), float4 means, merged B-prep kernel.
// Fixed shapes: B=64, C=3, HW=384, P=16 -> N=576, D=Hd=768, V=1000.
// ---------------------------------------------------------------------------

constexpr int CB   = 64;
constexpr int CC   = 3;
constexpr int CHW  = 384;
constexpr int CP   = 16;
constexpr int CG   = CHW / CP;      // 24
constexpr int CN   = CG * CG;       // 576
constexpr int CD   = CC * CP * CP;  // 768
constexpr int CHD  = 768;
constexpr int CV   = 1000;
constexpr int CVP  = 1024;          // padded vocab rows
constexpr int CNB  = CHD + CVP;     // 1792 concatenated B rows
constexpr int CBN  = CB * CN;       // 36864
constexpr int CNP1 = CN + 1;        // 577

// -------------------- device scratch ---------------------------------------
__device__ __half g_patches[(size_t)CBN * CD];    // fp16, [M][K]
__device__ float  g_emb[(size_t)CBN * CHD];
__device__ __half g_Bcat[(size_t)CNB * CD];       // [conv_w ; vocab_norm] K-major
__device__ float  g_pnorm[CBN];
__device__ unsigned long long g_packed[CBN];      // (ordered_score<<32)|(~v)
__device__ int   g_perm[CB * CN];
__device__ int   g_segstart[CB * CNP1];
__device__ int   g_nseg[CB];

// -------------------- helpers ----------------------------------------------
__device__ __forceinline__ void mma_f16(float* c, const unsigned* a, const unsigned* b) {
    asm volatile(
        "mma.sync.aligned.m16n8k16.row.col.f32.f16.f16.f32 "
        "{%0,%1,%2,%3}, {%4,%5,%6,%7}, {%8,%9}, {%0,%1,%2,%3};"
        : "+f"(c[0]), "+f"(c[1]), "+f"(c[2]), "+f"(c[3])
        : "r"(a[0]), "r"(a[1]), "r"(a[2]), "r"(a[3]), "r"(b[0]), "r"(b[1]));
}
__device__ __forceinline__ void ldsm_x4(unsigned& r0, unsigned& r1, unsigned& r2,
                                        unsigned& r3, const void* p) {
    unsigned a = (unsigned)__cvta_generic_to_shared(p);
    asm volatile("ldmatrix.sync.aligned.m8n8.x4.shared.b16 {%0,%1,%2,%3}, [%4];"
                 : "=r"(r0), "=r"(r1), "=r"(r2), "=r"(r3) : "r"(a));
}
__device__ __forceinline__ void cp16(void* smem_dst, const void* gmem_src) {
    unsigned s = (unsigned)__cvta_generic_to_shared(smem_dst);
    asm volatile("cp.async.ca.shared.global [%0], [%1], 16;\n" :: "r"(s), "l"(gmem_src));
}
__device__ __forceinline__ unsigned enc_f(float f) {
    unsigned u = __float_as_uint(f);
    return (u & 0x80000000u) ? ~u : (u | 0x80000000u);
}
__device__ __forceinline__ float dec_f(unsigned e) {
    unsigned b = (e & 0x80000000u) ? (e ^ 0x80000000u) : ~e;
    return __uint_as_float(b);
}

// -------------------- prep: build g_Bcat = [conv_w(fp16) ; vocab_norm(fp16)] -
__global__ void prep_b_kernel(const float* __restrict__ W,
                              const float* __restrict__ vocab) {
    int row = blockIdx.x;
    __half* dst = &g_Bcat[(size_t)row * CD];
    if (row < CHD) {
        const float* src = W + (size_t)row * CD;
        for (int d = threadIdx.x; d < CD; d += 256)
            dst[d] = __float2half_rn(src[d]);
        return;
    }
    int v = row - CHD;
    if (v >= CV) {
        for (int d = threadIdx.x; d < CD; d += 256) dst[d] = __float2half_rn(0.f);
        return;
    }
    __shared__ float red[256];
    float s = 0.f;
    for (int d = threadIdx.x; d < CD; d += 256) {
        float x = vocab[(size_t)v * CD + d];
        s += x * x;
    }
    red[threadIdx.x] = s; __syncthreads();
    for (int o = 128; o > 0; o >>= 1) {
        if (threadIdx.x < o) red[threadIdx.x] += red[threadIdx.x + o];
        __syncthreads();
    }
    float invn = 1.0f / sqrtf(red[0]);
    for (int d = threadIdx.x; d < CD; d += 256)
        dst[d] = __float2half_rn(vocab[(size_t)v * CD + d] * invn);
}

// -------------------- fused patch extraction + L2 norm + packed init --------
__global__ void __launch_bounds__(192) extract_pnorm_kernel(const float* __restrict__ px) {
    int patch = blockIdx.x;               // 0..CBN-1
    int b = patch / CN, n = patch % CN;
    int hp = n / CG, wp = n % CG;
    const float* base = px + ((size_t)b * CC * CHW + (size_t)hp * CP) * CHW + wp * CP;
    int tid = threadIdx.x, lane = tid & 31, w = tid >> 5;
    if (tid == 64) g_packed[patch] = 0ULL;     // zero before GEMM (stream-ordered)
    int d4 = tid << 2;
    int c = d4 >> 8, r = d4 & 255, ph = r >> 4, pw = r & 15;
    float4 x = *reinterpret_cast<const float4*>(
        &base[((size_t)c * CHW + ph) * CHW + pw]);
    __half2 h01 = __floats2half2_rn(x.x, x.y);
    __half2 h23 = __floats2half2_rn(x.z, x.w);
    *reinterpret_cast<uint2*>(&g_patches[(size_t)patch * CD + d4]) =
        make_uint2(*reinterpret_cast<unsigned*>(&h01), *reinterpret_cast<unsigned*>(&h23));
    float ss = x.x * x.x + x.y * x.y + x.z * x.z + x.w * x.w;
#pragma unroll
    for (int o = 16; o > 0; o >>= 1) ss += __shfl_xor_sync(0xffffffffu, ss, o);
    __shared__ float ws[6];
    if (lane == 0) ws[w] = ss;
    __syncthreads();
    if (tid == 0) {
        float t = ws[0] + ws[1] + ws[2] + ws[3] + ws[4] + ws[5];
        g_pnorm[patch] = sqrtf(t);
    }
}

// -------------------- GEMM config (frozen round-12 best) ---------------------
#define BM 128
#define BN 128
#define BK 32
#define PAD_ST 40
#define NSTAGE 3
constexpr int SM_A_H = BM * PAD_ST;     // 5120 halves per stage
constexpr int SM_B_H = BN * PAD_ST;     // 5120 halves per stage
constexpr int SMEM_GEMM = NSTAGE * (SM_A_H + SM_B_H) * 2;  // 61440 B

__global__ void __launch_bounds__(256, 2)
gemm_fused_kernel(const __half* __restrict__ A, const __half* __restrict__ Bg,
                  float* __restrict__ C, const float* __restrict__ bias,
                  const float* __restrict__ pos) {
    extern __shared__ __half sm[];
    __half* AsB = sm;                        // [NSTAGE][BM][PAD_ST]
    __half* BsB = sm + NSTAGE * SM_A_H;      // [NSTAGE][BN][PAD_ST]
    int tid = threadIdx.x, lane = tid & 31, warp = tid >> 5;
    int warpM = warp >> 2, warpN = warp & 3;
    int rowBase = blockIdx.y * BM, colBase = blockIdx.x * BN;
    int tig = lane & 3, grp = lane >> 2;
    int lrow = lane & 15, lhi = (lane >> 4) << 3;

    float acc[4][4][4];
#pragma unroll
    for (int mi = 0; mi < 4; mi++)
#pragma unroll
        for (int ni = 0; ni < 4; ni++)
#pragma unroll
            for (int q = 0; q < 4; q++) acc[mi][ni][q] = 0.f;

    const int nk = CD / BK;  // 24

#define G_LOAD(ST, K0)                                                               \
    {                                                                                \
        _Pragma("unroll")                                                            \
        for (int i = 0; i < 2; i++) {                                                \
            int idx = tid + i * 256;                                                 \
            int r = idx >> 2, c8 = (idx & 3) << 3;                                   \
            cp16(&AsB[(ST) * SM_A_H + r * PAD_ST + c8],                              \
                 &A[(size_t)(rowBase + r) * CD + (K0) + c8]);                        \
        }                                                                            \
        _Pragma("unroll")                                                            \
        for (int i = 0; i < 2; i++) {                                                \
            int idx = tid + i * 256;                                                 \
            int r = idx >> 2, c8 = (idx & 3) << 3;                                   \
            cp16(&BsB[(ST) * SM_B_H + r * PAD_ST + c8],                              \
                 &Bg[(size_t)(colBase + r) * CD + (K0) + c8]);                       \
        }                                                                            \
        asm volatile("cp.async.commit_group;\n");                                    \
    }

    G_LOAD(0, 0);
    G_LOAD(1, BK);
    for (int kt = 0; kt < nk; kt++) {
        if (kt + 1 < nk) {
            asm volatile("cp.async.wait_group 1;\n");
        } else {
            asm volatile("cp.async.wait_group 0;\n");
        }
        __syncthreads();
        if (kt + 2 < nk) {
            int st2 = (kt + 2) % NSTAGE;
            G_LOAD(st2, (kt + 2) * BK);
        }
        int st = kt % NSTAGE;
        const __half* Asm = &AsB[st * SM_A_H];
        const __half* Bsm = &BsB[st * SM_B_H];
        unsigned ua[2][4][4], ub[2][4][2];
#pragma unroll
        for (int kk = 0; kk < 2; kk++) {
            int kb = kk * 16;
#pragma unroll
            for (int mi = 0; mi < 4; mi++) {
                ldsm_x4(ua[kk][mi][0], ua[kk][mi][1], ua[kk][mi][2], ua[kk][mi][3],
                        &Asm[(warpM * 64 + mi * 16 + lrow) * PAD_ST + kb + lhi]);
            }
#pragma unroll
            for (int p = 0; p < 2; p++) {
                ldsm_x4(ub[kk][2 * p][0], ub[kk][2 * p + 1][0],
                        ub[kk][2 * p][1], ub[kk][2 * p + 1][1],
                        &Bsm[(warpN * 32 + p * 16 + lrow) * PAD_ST + kb + lhi]);
            }
        }
#pragma unroll
        for (int kk = 0; kk < 2; kk++)
#pragma unroll
            for (int mi = 0; mi < 4; mi++)
#pragma unroll
                for (int ni = 0; ni < 4; ni++)
                    mma_f16(acc[mi][ni], ua[kk][mi], ub[kk][ni]);
    }
#undef G_LOAD

    if (colBase < CHD) {
        // ---- emb epilogue: C = acc + bias + pos ----
#pragma unroll
        for (int mi = 0; mi < 4; mi++) {
            int r0 = rowBase + warpM * 64 + mi * 16 + grp;
            int r1 = r0 + 8;
            int p0 = (r0 % CN) + 1, p1 = (r1 % CN) + 1;
#pragma unroll
            for (int ni = 0; ni < 4; ni++) {
                int col = colBase + warpN * 32 + ni * 8 + 2 * tig;
                float2 v0, v1;
                v0.x = acc[mi][ni][0] + bias[col]     + pos[(size_t)p0 * CHD + col];
                v0.y = acc[mi][ni][1] + bias[col + 1] + pos[(size_t)p0 * CHD + col + 1];
                v1.x = acc[mi][ni][2] + bias[col]     + pos[(size_t)p1 * CHD + col];
                v1.y = acc[mi][ni][3] + bias[col + 1] + pos[(size_t)p1 * CHD + col + 1];
                *reinterpret_cast<float2*>(&C[(size_t)r0 * CHD + col]) = v0;
                *reinterpret_cast<float2*>(&C[(size_t)r1 * CHD + col]) = v1;
            }
        }
    } else {
        // ---- scores epilogue: fused per-row max/argmax (ties -> smallest v) ----
        int vcolBase = colBase - CHD;
#pragma unroll
        for (int mi = 0; mi < 4; mi++) {
#pragma unroll
            for (int h = 0; h < 2; h++) {
                int row = rowBase + warpM * 64 + mi * 16 + h * 8 + grp;
                unsigned long long p = 0ULL;
#pragma unroll
                for (int ni = 0; ni < 4; ni++) {
                    int col = vcolBase + warpN * 32 + ni * 8 + 2 * tig;
                    float s0 = acc[mi][ni][h * 2 + 0];
                    float s1 = acc[mi][ni][h * 2 + 1];
                    if (col < CV) {
                        unsigned long long q =
                            ((unsigned long long)enc_f(s0) << 32) | (0xFFFFFFFFu - (unsigned)col);
                        if (q > p) p = q;
                    }
                    if (col + 1 < CV) {
                        unsigned long long q =
                            ((unsigned long long)enc_f(s1) << 32) | (0xFFFFFFFFu - (unsigned)(col + 1));
                        if (q > p) p = q;
                    }
                }
                unsigned long long o;
                o = __shfl_xor_sync(0xffffffffu, p, 1); if (o > p) p = o;
                o = __shfl_xor_sync(0xffffffffu, p, 2); if (o > p) p = o;
                if (tig == 0 && p) atomicMax(&g_packed[row], p);
            }
        }
    }
}

// -------------------- fused label + per-row sort + unique-consecutive --------
__global__ void __launch_bounds__(1024)
compact_kernel(float* __restrict__ labels_out) {
    __shared__ unsigned int key[1024];
    __shared__ int sc[1024];
    int b = blockIdx.x, tid = threadIdx.x;

    int m = 0, v = 0;
    if (tid < CN) {
        unsigned long long p = g_packed[b * CN + tid];
        float score = dec_f((unsigned)(p >> 32));
        v = (int)(0xFFFFFFFFu - (unsigned)(p & 0xFFFFFFFFu));
        float smin = 1.0f - score / g_pnorm[b * CN + tid];
        m = (smin > 0.1f) ? 1 : 0;
    }
    sc[tid] = m; __syncthreads();
    for (int off = 1; off < 1024; off <<= 1) {
        int y = (tid >= off) ? sc[tid - off] : 0;
        __syncthreads();
        sc[tid] += y;
        __syncthreads();
    }
    int lab0 = m ? (CV + sc[tid] - m) : v;
    key[tid] = (tid < CN) ? ((((unsigned)lab0) << 16) | (unsigned)tid) : 0xFFFFFFFFu;
    __syncthreads();

    for (int k = 2; k <= 1024; k <<= 1) {
        for (int j = k >> 1; j > 0; j >>= 1) {
            int ixj = tid ^ j;
            if (ixj > tid) {
                unsigned a = key[tid], c2 = key[ixj];
                bool up = ((tid & k) == 0);
                if ((a > c2) == up) { key[tid] = c2; key[ixj] = a; }
            }
            __syncthreads();
        }
    }

    int lab     = (int)(key[tid] >> 16);
    int labprev = (tid > 0) ? (int)(key[tid - 1] >> 16) : -1;
    int step = (tid > 0 && tid < CN && lab != labprev) ? 1 : 0;
    sc[tid] = step; __syncthreads();
    for (int off = 1; off < 1024; off <<= 1) {
        int y = (tid >= off) ? sc[tid - off] : 0;
        __syncthreads();
        sc[tid] += y;
        __syncthreads();
    }
    if (tid < CN) {
        int l = sc[tid];
        int orig = (int)(key[tid] & 0xFFFFu);
        labels_out[(size_t)b * CN + orig] = (float)l;
        g_perm[b * CN + tid] = orig;
        if (tid == 0 || step) g_segstart[b * CNP1 + l] = tid;
    }
    __syncthreads();
    if (tid == 0) {
        int ns = sc[CN - 1] + 1;
        g_nseg[b] = ns;
        g_segstart[b * CNP1 + ns] = CN;
    }
}

// -------------------- segment means + cls + pad + attn row -------------------
// grid (CNP1, CB): block (r, b) writes out[b][r][:] (float4) AND attn[b,0,r,:].
__global__ void __launch_bounds__(192)
means_attn_kernel(float* __restrict__ out, float* __restrict__ attn,
                  const float* __restrict__ cls, const float* __restrict__ pos,
                  const float* __restrict__ pad) {
    int b = blockIdx.y, r = blockIdx.x;
    int tid = threadIdx.x;
    int ns = g_nseg[b];

    // attention mask row (value depends only on column j)
    float* arow = attn + ((size_t)b * CNP1 + r) * CNP1;
    for (int j = tid; j < CNP1; j += 192)
        arow[j] = (j > 0 && (j - 1) >= ns) ? -3.4028234663852886e38f : 0.0f;

    float4* o4 = reinterpret_cast<float4*>(out + ((size_t)b * CNP1 + r) * CHD);
    if (r == 0) {
        const float4* c4 = reinterpret_cast<const float4*>(cls);
        const float4* p4 = reinterpret_cast<const float4*>(pos);
        float4 cv = c4[tid], pv = p4[tid];
        o4[tid] = make_float4(cv.x + pv.x, cv.y + pv.y, cv.z + pv.z, cv.w + pv.w);
        return;
    }
    int l = r - 1;
    if (l < ns) {
        int s0 = g_segstart[b * CNP1 + l];
        int s1 = g_segstart[b * CNP1 + l + 1];
        float inv = 1.0f / (float)(s1 - s0);
        float4 s = make_float4(0.f, 0.f, 0.f, 0.f);
        for (int j = s0; j < s1; j++) {
            const float4* e4 = reinterpret_cast<const float4*>(
                &g_emb[((size_t)b * CN + g_perm[b * CN + j]) * CHD]);
            float4 v = e4[tid];
            s.x += v.x; s.y += v.y; s.z += v.z; s.w += v.w;
        }
        o4[tid] = make_float4(s.x * inv, s.y * inv, s.z * inv, s.w * inv);
    } else {
        o4[tid] = reinterpret_cast<const float4*>(pad)[tid];
    }
}

// ---------------------------------------------------------------------------
extern "C" void kernel_launch(void* const* d_in, const int* in_sizes, int n_in,
                              void* d_out, int out_size) {
    (void)in_sizes; (void)n_in; (void)out_size;
    const float* px     = (const float*)d_in[0];
    const float* conv_w = (const float*)d_in[1];
    const float* conv_b = (const float*)d_in[2];
    const float* cls    = (const float*)d_in[3];
    const float* pos    = (const float*)d_in[4];
    const float* vocab  = (const float*)d_in[5];
    const float* pad    = (const float*)d_in[6];

    float* out        = (float*)d_out;
    float* labels_out = out + (size_t)CB * CNP1 * CHD;
    float* attn_out   = labels_out + (size_t)CB * CN;

    __half *patches, *Bcat;
    float *emb;
    cudaGetSymbolAddress((void**)&patches, g_patches);
    cudaGetSymbolAddress((void**)&emb,     g_emb);
    cudaGetSymbolAddress((void**)&Bcat,    g_Bcat);

    cudaFuncSetAttribute(gemm_fused_kernel,
                         cudaFuncAttributeMaxDynamicSharedMemorySize, SMEM_GEMM);

    // launch order keeps gemm at capture index 3 for ncu (-s 5 -c 1 window)
    prep_b_kernel<<<CNB, 256>>>(conv_w, vocab);
    extract_pnorm_kernel<<<CBN, 192>>>(px);
    gemm_fused_kernel<<<dim3(CNB / BN, CBN / BM), 256, SMEM_GEMM>>>(
        patches, Bcat, emb, conv_b, pos);

    compact_kernel<<<CB, 1024>>>(labels_out);
    means_attn_kernel<<<dim3(CNP1, CB), 192>>>(out, attn_out, cls, pos, pad);
}

// round 15
// speedup vs baseline: 1.2457x; 1.0413x over previous
#include <cuda_runtime.h>
#include <cuda_fp16.h>
#include <math.h>
#include <stdint.h>

// ---------------------------------------------------------------------------
// InterImageTokenizer — round 14.
// GEMM mainloop frozen (354us, structural mma.sync plateau). This round:
// fp16 emb storage (half write + half read), 2-patch MLP=2 extract,
// prep_b merged into extract launch.
// Fixed shapes: B=64, C=3, HW=384, P=16 -> N=576, D=Hd=768, V=1000.
// ---------------------------------------------------------------------------

constexpr int CB   = 64;
constexpr int CC   = 3;
constexpr int CHW  = 384;
constexpr int CP   = 16;
constexpr int CG   = CHW / CP;      // 24
constexpr int CN   = CG * CG;       // 576
constexpr int CD   = CC * CP * CP;  // 768
constexpr int CHD  = 768;
constexpr int CV   = 1000;
constexpr int CVP  = 1024;          // padded vocab rows
constexpr int CNB  = CHD + CVP;     // 1792 concatenated B rows
constexpr int CBN  = CB * CN;       // 36864
constexpr int CNP1 = CN + 1;        // 577

// -------------------- device scratch ---------------------------------------
__device__ __half g_patches[(size_t)CBN * CD];    // fp16, [M][K]
__device__ __half g_emb[(size_t)CBN * CHD];       // fp16 emb (means re-reads)
__device__ __half g_Bcat[(size_t)CNB * CD];       // [conv_w ; vocab_norm] K-major
__device__ float  g_pnorm[CBN];
__device__ unsigned long long g_packed[CBN];      // (ordered_score<<32)|(~v)
__device__ int   g_perm[CB * CN];
__device__ int   g_segstart[CB * CNP1];
__device__ int   g_nseg[CB];

// -------------------- helpers ----------------------------------------------
__device__ __forceinline__ void mma_f16(float* c, const unsigned* a, const unsigned* b) {
    asm volatile(
        "mma.sync.aligned.m16n8k16.row.col.f32.f16.f16.f32 "
        "{%0,%1,%2,%3}, {%4,%5,%6,%7}, {%8,%9}, {%0,%1,%2,%3};"
        : "+f"(c[0]), "+f"(c[1]), "+f"(c[2]), "+f"(c[3])
        : "r"(a[0]), "r"(a[1]), "r"(a[2]), "r"(a[3]), "r"(b[0]), "r"(b[1]));
}
__device__ __forceinline__ void ldsm_x4(unsigned& r0, unsigned& r1, unsigned& r2,
                                        unsigned& r3, const void* p) {
    unsigned a = (unsigned)__cvta_generic_to_shared(p);
    asm volatile("ldmatrix.sync.aligned.m8n8.x4.shared.b16 {%0,%1,%2,%3}, [%4];"
                 : "=r"(r0), "=r"(r1), "=r"(r2), "=r"(r3) : "r"(a));
}
__device__ __forceinline__ void cp16(void* smem_dst, const void* gmem_src) {
    unsigned s = (unsigned)__cvta_generic_to_shared(smem_dst);
    asm volatile("cp.async.ca.shared.global [%0], [%1], 16;\n" :: "r"(s), "l"(gmem_src));
}
__device__ __forceinline__ unsigned enc_f(float f) {
    unsigned u = __float_as_uint(f);
    return (u & 0x80000000u) ? ~u : (u | 0x80000000u);
}
__device__ __forceinline__ float dec_f(unsigned e) {
    unsigned b = (e & 0x80000000u) ? (e ^ 0x80000000u) : ~e;
    return __uint_as_float(b);
}

// -------------------- merged prep(Bcat) + patch extraction -------------------
// blocks [0, CBN/2): two patches each (MLP=2). blocks [CBN/2, +CNB): Bcat rows.
constexpr int EX_BLOCKS = CBN / 2;          // 18432
__global__ void __launch_bounds__(192)
extract_prep_kernel(const float* __restrict__ px, const float* __restrict__ W,
                    const float* __restrict__ vocab) {
    int tid = threadIdx.x;
    if (blockIdx.x >= EX_BLOCKS) {
        // ---------------- Bcat prep ----------------
        int row = blockIdx.x - EX_BLOCKS;
        __half* dst = &g_Bcat[(size_t)row * CD];
        if (row < CHD) {
            const float* src = W + (size_t)row * CD;
            for (int d = tid; d < CD; d += 192)
                dst[d] = __float2half_rn(src[d]);
            return;
        }
        int v = row - CHD;
        if (v >= CV) {
            for (int d = tid; d < CD; d += 192) dst[d] = __float2half_rn(0.f);
            return;
        }
        __shared__ float red[192];
        float s = 0.f;
        for (int d = tid; d < CD; d += 192) {
            float x = vocab[(size_t)v * CD + d];
            s += x * x;
        }
        red[tid] = s; __syncthreads();
        if (tid < 64) red[tid] += red[tid + 64] + red[tid + 128];
        __syncthreads();
        for (int o = 32; o > 0; o >>= 1) {
            if (tid < o) red[tid] += red[tid + o];
            __syncthreads();
        }
        float invn = 1.0f / sqrtf(red[0]);
        for (int d = tid; d < CD; d += 192)
            dst[d] = __float2half_rn(vocab[(size_t)v * CD + d] * invn);
        return;
    }
    // ---------------- patch extraction: two patches per block ---------------
    int p0 = blockIdx.x * 2, p1 = p0 + 1;
    int lane = tid & 31, w = tid >> 5;
    if (tid == 64) { g_packed[p0] = 0ULL; g_packed[p1] = 0ULL; }
    int d4 = tid << 2;
    int c = d4 >> 8, r = d4 & 255, ph = r >> 4, pw = r & 15;

    int b0 = p0 / CN, n0 = p0 % CN;
    int b1 = p1 / CN, n1 = p1 % CN;
    const float* a0 = px + ((size_t)b0 * CC * CHW + (size_t)(n0 / CG) * CP) * CHW
                         + (n0 % CG) * CP + ((size_t)c * CHW + ph) * CHW + pw;
    const float* a1 = px + ((size_t)b1 * CC * CHW + (size_t)(n1 / CG) * CP) * CHW
                         + (n1 % CG) * CP + ((size_t)c * CHW + ph) * CHW + pw;
    float4 x0 = *reinterpret_cast<const float4*>(a0);
    float4 x1 = *reinterpret_cast<const float4*>(a1);

    __half2 h0a = __floats2half2_rn(x0.x, x0.y), h0b = __floats2half2_rn(x0.z, x0.w);
    __half2 h1a = __floats2half2_rn(x1.x, x1.y), h1b = __floats2half2_rn(x1.z, x1.w);
    *reinterpret_cast<uint2*>(&g_patches[(size_t)p0 * CD + d4]) =
        make_uint2(*reinterpret_cast<unsigned*>(&h0a), *reinterpret_cast<unsigned*>(&h0b));
    *reinterpret_cast<uint2*>(&g_patches[(size_t)p1 * CD + d4]) =
        make_uint2(*reinterpret_cast<unsigned*>(&h1a), *reinterpret_cast<unsigned*>(&h1b));

    float s0 = x0.x * x0.x + x0.y * x0.y + x0.z * x0.z + x0.w * x0.w;
    float s1 = x1.x * x1.x + x1.y * x1.y + x1.z * x1.z + x1.w * x1.w;
#pragma unroll
    for (int o = 16; o > 0; o >>= 1) {
        s0 += __shfl_xor_sync(0xffffffffu, s0, o);
        s1 += __shfl_xor_sync(0xffffffffu, s1, o);
    }
    __shared__ float ws0[6], ws1[6];
    if (lane == 0) { ws0[w] = s0; ws1[w] = s1; }
    __syncthreads();
    if (tid == 0) {
        g_pnorm[p0] = sqrtf(ws0[0] + ws0[1] + ws0[2] + ws0[3] + ws0[4] + ws0[5]);
        g_pnorm[p1] = sqrtf(ws1[0] + ws1[1] + ws1[2] + ws1[3] + ws1[4] + ws1[5]);
    }
}

// -------------------- GEMM config (mainloop frozen round-12 best) ------------
#define BM 128
#define BN 128
#define BK 32
#define PAD_ST 40
#define NSTAGE 3
constexpr int SM_A_H = BM * PAD_ST;     // 5120 halves per stage
constexpr int SM_B_H = BN * PAD_ST;     // 5120 halves per stage
constexpr int SMEM_GEMM = NSTAGE * (SM_A_H + SM_B_H) * 2;  // 61440 B

__global__ void __launch_bounds__(256, 2)
gemm_fused_kernel(const __half* __restrict__ A, const __half* __restrict__ Bg,
                  __half* __restrict__ C, const float* __restrict__ bias,
                  const float* __restrict__ pos) {
    extern __shared__ __half sm[];
    __half* AsB = sm;                        // [NSTAGE][BM][PAD_ST]
    __half* BsB = sm + NSTAGE * SM_A_H;      // [NSTAGE][BN][PAD_ST]
    int tid = threadIdx.x, lane = tid & 31, warp = tid >> 5;
    int warpM = warp >> 2, warpN = warp & 3;
    int rowBase = blockIdx.y * BM, colBase = blockIdx.x * BN;
    int tig = lane & 3, grp = lane >> 2;
    int lrow = lane & 15, lhi = (lane >> 4) << 3;

    float acc[4][4][4];
#pragma unroll
    for (int mi = 0; mi < 4; mi++)
#pragma unroll
        for (int ni = 0; ni < 4; ni++)
#pragma unroll
            for (int q = 0; q < 4; q++) acc[mi][ni][q] = 0.f;

    const int nk = CD / BK;  // 24

#define G_LOAD(ST, K0)                                                               \
    {                                                                                \
        _Pragma("unroll")                                                            \
        for (int i = 0; i < 2; i++) {                                                \
            int idx = tid + i * 256;                                                 \
            int r = idx >> 2, c8 = (idx & 3) << 3;                                   \
            cp16(&AsB[(ST) * SM_A_H + r * PAD_ST + c8],                              \
                 &A[(size_t)(rowBase + r) * CD + (K0) + c8]);                        \
        }                                                                            \
        _Pragma("unroll")                                                            \
        for (int i = 0; i < 2; i++) {                                                \
            int idx = tid + i * 256;                                                 \
            int r = idx >> 2, c8 = (idx & 3) << 3;                                   \
            cp16(&BsB[(ST) * SM_B_H + r * PAD_ST + c8],                              \
                 &Bg[(size_t)(colBase + r) * CD + (K0) + c8]);                       \
        }                                                                            \
        asm volatile("cp.async.commit_group;\n");                                    \
    }

    G_LOAD(0, 0);
    G_LOAD(1, BK);
    for (int kt = 0; kt < nk; kt++) {
        if (kt + 1 < nk) {
            asm volatile("cp.async.wait_group 1;\n");
        } else {
            asm volatile("cp.async.wait_group 0;\n");
        }
        __syncthreads();
        if (kt + 2 < nk) {
            int st2 = (kt + 2) % NSTAGE;
            G_LOAD(st2, (kt + 2) * BK);
        }
        int st = kt % NSTAGE;
        const __half* Asm = &AsB[st * SM_A_H];
        const __half* Bsm = &BsB[st * SM_B_H];
        unsigned ua[2][4][4], ub[2][4][2];
#pragma unroll
        for (int kk = 0; kk < 2; kk++) {
            int kb = kk * 16;
#pragma unroll
            for (int mi = 0; mi < 4; mi++) {
                ldsm_x4(ua[kk][mi][0], ua[kk][mi][1], ua[kk][mi][2], ua[kk][mi][3],
                        &Asm[(warpM * 64 + mi * 16 + lrow) * PAD_ST + kb + lhi]);
            }
#pragma unroll
            for (int p = 0; p < 2; p++) {
                ldsm_x4(ub[kk][2 * p][0], ub[kk][2 * p + 1][0],
                        ub[kk][2 * p][1], ub[kk][2 * p + 1][1],
                        &Bsm[(warpN * 32 + p * 16 + lrow) * PAD_ST + kb + lhi]);
            }
        }
#pragma unroll
        for (int kk = 0; kk < 2; kk++)
#pragma unroll
            for (int mi = 0; mi < 4; mi++)
#pragma unroll
                for (int ni = 0; ni < 4; ni++)
                    mma_f16(acc[mi][ni], ua[kk][mi], ub[kk][ni]);
    }
#undef G_LOAD

    if (colBase < CHD) {
        // ---- emb epilogue: C(fp16) = acc + bias + pos ----
#pragma unroll
        for (int mi = 0; mi < 4; mi++) {
            int r0 = rowBase + warpM * 64 + mi * 16 + grp;
            int r1 = r0 + 8;
            int p0 = (r0 % CN) + 1, p1 = (r1 % CN) + 1;
#pragma unroll
            for (int ni = 0; ni < 4; ni++) {
                int col = colBase + warpN * 32 + ni * 8 + 2 * tig;
                __half2 h0 = __floats2half2_rn(
                    acc[mi][ni][0] + bias[col]     + pos[(size_t)p0 * CHD + col],
                    acc[mi][ni][1] + bias[col + 1] + pos[(size_t)p0 * CHD + col + 1]);
                __half2 h1 = __floats2half2_rn(
                    acc[mi][ni][2] + bias[col]     + pos[(size_t)p1 * CHD + col],
                    acc[mi][ni][3] + bias[col + 1] + pos[(size_t)p1 * CHD + col + 1]);
                *reinterpret_cast<__half2*>(&C[(size_t)r0 * CHD + col]) = h0;
                *reinterpret_cast<__half2*>(&C[(size_t)r1 * CHD + col]) = h1;
            }
        }
    } else {
        // ---- scores epilogue: fused per-row max/argmax (ties -> smallest v) ----
        int vcolBase = colBase - CHD;
#pragma unroll
        for (int mi = 0; mi < 4; mi++) {
#pragma unroll
            for (int h = 0; h < 2; h++) {
                int row = rowBase + warpM * 64 + mi * 16 + h * 8 + grp;
                unsigned long long p = 0ULL;
#pragma unroll
                for (int ni = 0; ni < 4; ni++) {
                    int col = vcolBase + warpN * 32 + ni * 8 + 2 * tig;
                    float s0 = acc[mi][ni][h * 2 + 0];
                    float s1 = acc[mi][ni][h * 2 + 1];
                    if (col < CV) {
                        unsigned long long q =
                            ((unsigned long long)enc_f(s0) << 32) | (0xFFFFFFFFu - (unsigned)col);
                        if (q > p) p = q;
                    }
                    if (col + 1 < CV) {
                        unsigned long long q =
                            ((unsigned long long)enc_f(s1) << 32) | (0xFFFFFFFFu - (unsigned)(col + 1));
                        if (q > p) p = q;
                    }
                }
                unsigned long long o;
                o = __shfl_xor_sync(0xffffffffu, p, 1); if (o > p) p = o;
                o = __shfl_xor_sync(0xffffffffu, p, 2); if (o > p) p = o;
                if (tig == 0 && p) atomicMax(&g_packed[row], p);
            }
        }
    }
}

// -------------------- fused label + per-row sort + unique-consecutive --------
__global__ void __launch_bounds__(1024)
compact_kernel(float* __restrict__ labels_out) {
    __shared__ unsigned int key[1024];
    __shared__ int sc[1024];
    int b = blockIdx.x, tid = threadIdx.x;

    int m = 0, v = 0;
    if (tid < CN) {
        unsigned long long p = g_packed[b * CN + tid];
        float score = dec_f((unsigned)(p >> 32));
        v = (int)(0xFFFFFFFFu - (unsigned)(p & 0xFFFFFFFFu));
        float smin = 1.0f - score / g_pnorm[b * CN + tid];
        m = (smin > 0.1f) ? 1 : 0;
    }
    sc[tid] = m; __syncthreads();
    for (int off = 1; off < 1024; off <<= 1) {
        int y = (tid >= off) ? sc[tid - off] : 0;
        __syncthreads();
        sc[tid] += y;
        __syncthreads();
    }
    int lab0 = m ? (CV + sc[tid] - m) : v;
    key[tid] = (tid < CN) ? ((((unsigned)lab0) << 16) | (unsigned)tid) : 0xFFFFFFFFu;
    __syncthreads();

    for (int k = 2; k <= 1024; k <<= 1) {
        for (int j = k >> 1; j > 0; j >>= 1) {
            int ixj = tid ^ j;
            if (ixj > tid) {
                unsigned a = key[tid], c2 = key[ixj];
                bool up = ((tid & k) == 0);
                if ((a > c2) == up) { key[tid] = c2; key[ixj] = a; }
            }
            __syncthreads();
        }
    }

    int lab     = (int)(key[tid] >> 16);
    int labprev = (tid > 0) ? (int)(key[tid - 1] >> 16) : -1;
    int step = (tid > 0 && tid < CN && lab != labprev) ? 1 : 0;
    sc[tid] = step; __syncthreads();
    for (int off = 1; off < 1024; off <<= 1) {
        int y = (tid >= off) ? sc[tid - off] : 0;
        __syncthreads();
        sc[tid] += y;
        __syncthreads();
    }
    if (tid < CN) {
        int l = sc[tid];
        int orig = (int)(key[tid] & 0xFFFFu);
        labels_out[(size_t)b * CN + orig] = (float)l;
        g_perm[b * CN + tid] = orig;
        if (tid == 0 || step) g_segstart[b * CNP1 + l] = tid;
    }
    __syncthreads();
    if (tid == 0) {
        int ns = sc[CN - 1] + 1;
        g_nseg[b] = ns;
        g_segstart[b * CNP1 + ns] = CN;
    }
}

// -------------------- segment means + cls + pad + attn row -------------------
// grid (CNP1, CB): block (r, b) writes out[b][r][:] (float4) AND attn[b,0,r,:].
__global__ void __launch_bounds__(192)
means_attn_kernel(float* __restrict__ out, float* __restrict__ attn,
                  const float* __restrict__ cls, const float* __restrict__ pos,
                  const float* __restrict__ pad) {
    int b = blockIdx.y, r = blockIdx.x;
    int tid = threadIdx.x;
    int ns = g_nseg[b];

    // attention mask row (value depends only on column j)
    float* arow = attn + ((size_t)b * CNP1 + r) * CNP1;
    for (int j = tid; j < CNP1; j += 192)
        arow[j] = (j > 0 && (j - 1) >= ns) ? -3.4028234663852886e38f : 0.0f;

    float4* o4 = reinterpret_cast<float4*>(out + ((size_t)b * CNP1 + r) * CHD);
    if (r == 0) {
        const float4* c4 = reinterpret_cast<const float4*>(cls);
        const float4* p4 = reinterpret_cast<const float4*>(pos);
        float4 cv = c4[tid], pv = p4[tid];
        o4[tid] = make_float4(cv.x + pv.x, cv.y + pv.y, cv.z + pv.z, cv.w + pv.w);
        return;
    }
    int l = r - 1;
    if (l < ns) {
        int s0 = g_segstart[b * CNP1 + l];
        int s1 = g_segstart[b * CNP1 + l + 1];
        float inv = 1.0f / (float)(s1 - s0);
        float4 s = make_float4(0.f, 0.f, 0.f, 0.f);
        for (int j = s0; j < s1; j++) {
            const uint2* e2 = reinterpret_cast<const uint2*>(
                &g_emb[((size_t)b * CN + g_perm[b * CN + j]) * CHD + (tid << 2)]);
            uint2 hv = *e2;
            float2 f01 = __half22float2(*reinterpret_cast<__half2*>(&hv.x));
            float2 f23 = __half22float2(*reinterpret_cast<__half2*>(&hv.y));
            s.x += f01.x; s.y += f01.y; s.z += f23.x; s.w += f23.y;
        }
        o4[tid] = make_float4(s.x * inv, s.y * inv, s.z * inv, s.w * inv);
    } else {
        o4[tid] = reinterpret_cast<const float4*>(pad)[tid];
    }
}

// ---------------------------------------------------------------------------
extern "C" void kernel_launch(void* const* d_in, const int* in_sizes, int n_in,
                              void* d_out, int out_size) {
    (void)in_sizes; (void)n_in; (void)out_size;
    const float* px     = (const float*)d_in[0];
    const float* conv_w = (const float*)d_in[1];
    const float* conv_b = (const float*)d_in[2];
    const float* cls    = (const float*)d_in[3];
    const float* pos    = (const float*)d_in[4];
    const float* vocab  = (const float*)d_in[5];
    const float* pad    = (const float*)d_in[6];

    float* out        = (float*)d_out;
    float* labels_out = out + (size_t)CB * CNP1 * CHD;
    float* attn_out   = labels_out + (size_t)CB * CN;

    __half *patches, *Bcat, *emb;
    cudaGetSymbolAddress((void**)&patches, g_patches);
    cudaGetSymbolAddress((void**)&emb,     g_emb);
    cudaGetSymbolAddress((void**)&Bcat,    g_Bcat);

    cudaFuncSetAttribute(gemm_fused_kernel,
                         cudaFuncAttributeMaxDynamicSharedMemorySize, SMEM_GEMM);

    extract_prep_kernel<<<EX_BLOCKS + CNB, 192>>>(px, conv_w, vocab);
    gemm_fused_kernel<<<dim3(CNB / BN, CBN / BM), 256, SMEM_GEMM>>>(
        patches, Bcat, emb, conv_b, pos);
    compact_kernel<<<CB, 1024>>>(labels_out);
    means_attn_kernel<<<dim3(CNP1, CB), 192>>>(out, attn_out, cls, pos, pad);
}